// round 1
// baseline (speedup 1.0000x reference)
#include <cuda_runtime.h>
#include <math.h>

// ---------------- problem constants ----------------
#define NTOK   8192          // B*S tokens
#define DM     1024          // d_model == inter (all GEMM dims are 1024 here)
#define NE     8             // experts
#define MAXROWS 17408        // 2*NTOK gathered rows + 8*127 padding, rounded up
#define RGRID  144           // worst-case routed row tiles (<=136)

// ---------------- device scratch (no allocs allowed) ----------------
__device__ float g_Xg[(size_t)MAXROWS * DM];
__device__ float g_h1[(size_t)MAXROWS * DM];
__device__ float g_h3[(size_t)MAXROWS * DM];
__device__ float g_Yg[(size_t)MAXROWS * DM];
__device__ float g_s1[(size_t)NTOK * DM];
__device__ float g_s3[(size_t)NTOK * DM];
__device__ float g_z [(size_t)NTOK * DM];

__device__ int   g_top_idx[NTOK * 2];
__device__ float g_top_w  [NTOK * 2];
__device__ int   g_slot_row[NTOK * 2];
__device__ int   g_counts[NE];
__device__ int   g_cursor[NE];
__device__ int   g_rowbase[NE];
__device__ int   g_rmap[160];
__device__ int   g_smap[64];
__device__ int   g_ntiles[1];
__device__ int   g_n64[1];

// ---------------- kernels ----------------

__global__ void k_zero()
{
    int i = threadIdx.x;
    if (i < NE) { g_counts[i] = 0; g_cursor[i] = 0; }
}

// One block per token: 8 warps compute 8 expert logits, thread 0 does softmax+top2.
__global__ void k_gate(const float* __restrict__ x, const float* __restrict__ gw)
{
    int t = blockIdx.x;
    int warp = threadIdx.x >> 5, lane = threadIdx.x & 31;
    __shared__ float logits[NE];

    const float* xr = x + (size_t)t * DM;
    const float* g  = gw + (size_t)warp * DM;
    float s = 0.f;
    for (int d = lane; d < DM; d += 32) s += xr[d] * g[d];
    #pragma unroll
    for (int o = 16; o; o >>= 1) s += __shfl_xor_sync(0xffffffffu, s, o);
    if (lane == 0) logits[warp] = s;
    __syncthreads();

    if (threadIdx.x == 0) {
        float m = logits[0];
        #pragma unroll
        for (int e = 1; e < NE; e++) m = fmaxf(m, logits[e]);
        float sum = 0.f, p[NE];
        #pragma unroll
        for (int e = 0; e < NE; e++) { p[e] = expf(logits[e] - m); sum += p[e]; }
        // top-2 (first index wins ties, matching lax.top_k)
        int i0 = 0;
        #pragma unroll
        for (int e = 1; e < NE; e++) if (logits[e] > logits[i0]) i0 = e;
        int i1 = (i0 == 0) ? 1 : 0;
        #pragma unroll
        for (int e = 0; e < NE; e++)
            if (e != i0 && logits[e] > logits[i1]) i1 = e;
        float inv = 1.f / sum;
        g_top_idx[2*t]   = i0;  g_top_w[2*t]   = p[i0] * inv;
        g_top_idx[2*t+1] = i1;  g_top_w[2*t+1] = p[i1] * inv;
        atomicAdd(&g_counts[i0], 1);
        atomicAdd(&g_counts[i1], 1);
    }
}

// Build 128-aligned per-expert regions + routed tile map + shared map.
__global__ void k_scan()
{
    int tid = threadIdx.x;
    if (tid == 0) {
        int base = 0, nt = 0;
        for (int e = 0; e < NE; e++) {
            g_rowbase[e] = base;
            int p = ((g_counts[e] + 127) >> 7) << 7;
            for (int i = 0; i < (p >> 7); i++)
                g_rmap[nt++] = (e << 20) | (base + (i << 7));
            base += p;
        }
        g_ntiles[0] = nt;
        g_n64[0] = 64;
    }
    if (tid < 64) g_smap[tid] = tid << 7;   // expert 0, row = tid*128
}

// Zero padded gather rows so pad-row GEMM outputs are finite (never read anyway).
__global__ void k_zeropad()
{
    int e = blockIdx.x;
    int c = g_counts[e];
    int p = ((c + 127) >> 7) << 7;
    int r = c + blockIdx.y;
    if (r < p) {
        float* row = g_Xg + (size_t)(g_rowbase[e] + r) * DM;
        for (int d = threadIdx.x; d < DM; d += blockDim.x) row[d] = 0.f;
    }
}

// One block per (token, slot): claim a row in the expert's region, copy x row.
__global__ void k_gather(const float* __restrict__ x)
{
    int slot = blockIdx.x, t = slot >> 1;
    __shared__ int srow;
    if (threadIdx.x == 0) {
        int e  = g_top_idx[slot];
        int rk = atomicAdd(&g_cursor[e], 1);
        int row = g_rowbase[e] + rk;
        g_slot_row[slot] = row;
        srow = row;
    }
    __syncthreads();
    const float4* src = (const float4*)(x + (size_t)t * DM);
    float4*       dst = (float4*)(g_Xg + (size_t)srow * DM);
    for (int i = threadIdx.x; i < DM/4; i += blockDim.x) dst[i] = src[i];
}

// Generic tile-mapped SGEMM: C[r0:r0+128, c0:c0+128] = A @ W[e] + bias[e]
// A row-major [*, DM]; W row-major [DM, DM] per expert at W + e*wstride.
__global__ __launch_bounds__(256, 2)
void k_gemm(const float* __restrict__ A, const float* __restrict__ W,
            const float* __restrict__ bias, float* __restrict__ C,
            const int* __restrict__ map, const int* __restrict__ ntiles,
            int wstride, int bstride)
{
    if ((int)blockIdx.x >= *ntiles) return;
    int entry = map[blockIdx.x];
    int e  = entry >> 20;
    int r0 = entry & 0xFFFFF;
    int c0 = blockIdx.y << 7;
    const float* Wp = W + (size_t)e * wstride;
    const float* bp = bias + (size_t)e * bstride;

    __shared__ float As[8][128];
    __shared__ float Bs[8][128];

    int tid  = threadIdx.x;
    int arow = tid >> 1, acol = (tid & 1) << 2;
    int brow = tid >> 5, bcol = (tid & 31) << 2;
    int ty   = tid >> 4, tx   = tid & 15;

    const float* Aptr = A  + (size_t)(r0 + arow) * DM + acol;
    const float* Bptr = Wp + (size_t)brow * DM + c0 + bcol;

    float4 aReg = *(const float4*)Aptr;
    float4 bReg = *(const float4*)Bptr;

    float acc[8][8];
    #pragma unroll
    for (int i = 0; i < 8; i++)
        #pragma unroll
        for (int j = 0; j < 8; j++) acc[i][j] = 0.f;

    for (int k0 = 0; k0 < DM; k0 += 8) {
        As[acol+0][arow] = aReg.x;
        As[acol+1][arow] = aReg.y;
        As[acol+2][arow] = aReg.z;
        As[acol+3][arow] = aReg.w;
        *(float4*)&Bs[brow][bcol] = bReg;
        __syncthreads();
        if (k0 + 8 < DM) {
            aReg = *(const float4*)(Aptr + k0 + 8);
            bReg = *(const float4*)(Bptr + (size_t)(k0 + 8) * DM);
        }
        #pragma unroll
        for (int kk = 0; kk < 8; kk++) {
            float a[8], b[8];
            *(float4*)&a[0] = *(float4*)&As[kk][ty*8];
            *(float4*)&a[4] = *(float4*)&As[kk][ty*8+4];
            *(float4*)&b[0] = *(float4*)&Bs[kk][tx*8];
            *(float4*)&b[4] = *(float4*)&Bs[kk][tx*8+4];
            #pragma unroll
            for (int i = 0; i < 8; i++)
                #pragma unroll
                for (int j = 0; j < 8; j++)
                    acc[i][j] += a[i] * b[j];
        }
        __syncthreads();
    }

    #pragma unroll
    for (int i = 0; i < 8; i++) {
        float* Crow = C + (size_t)(r0 + ty*8 + i) * DM + c0 + tx*8;
        float4 v0, v1;
        v0.x = acc[i][0] + bp[c0 + tx*8 + 0];
        v0.y = acc[i][1] + bp[c0 + tx*8 + 1];
        v0.z = acc[i][2] + bp[c0 + tx*8 + 2];
        v0.w = acc[i][3] + bp[c0 + tx*8 + 3];
        v1.x = acc[i][4] + bp[c0 + tx*8 + 4];
        v1.y = acc[i][5] + bp[c0 + tx*8 + 5];
        v1.z = acc[i][6] + bp[c0 + tx*8 + 6];
        v1.w = acc[i][7] + bp[c0 + tx*8 + 7];
        *(float4*)&Crow[0] = v0;
        *(float4*)&Crow[4] = v1;
    }
}

// a = silu(a) * b  (vectorized)
__global__ void k_silu(float* __restrict__ a, const float* __restrict__ b, int n4)
{
    int i = blockIdx.x * blockDim.x + threadIdx.x;
    if (i < n4) {
        float4 va = ((float4*)a)[i];
        float4 vb = ((const float4*)b)[i];
        va.x = va.x / (1.f + expf(-va.x)) * vb.x;
        va.y = va.y / (1.f + expf(-va.y)) * vb.y;
        va.z = va.z / (1.f + expf(-va.z)) * vb.z;
        va.w = va.w / (1.f + expf(-va.w)) * vb.w;
        ((float4*)a)[i] = va;
    }
}

// out[t] = w0*Yg[row0] + w1*Yg[row1] + z[t]
__global__ void k_combine(const float* __restrict__ Yg, const float* __restrict__ z,
                          float* __restrict__ out)
{
    int t = blockIdx.x;
    int r0 = g_slot_row[2*t], r1 = g_slot_row[2*t+1];
    float w0 = g_top_w[2*t], w1 = g_top_w[2*t+1];
    const float4* y0 = (const float4*)(Yg + (size_t)r0 * DM);
    const float4* y1 = (const float4*)(Yg + (size_t)r1 * DM);
    const float4* zz = (const float4*)(z  + (size_t)t  * DM);
    float4*       o  = (float4*)(out + (size_t)t * DM);
    for (int d = threadIdx.x; d < DM/4; d += blockDim.x) {
        float4 a = y0[d], b = y1[d], c = zz[d], r;
        r.x = w0*a.x + w1*b.x + c.x;
        r.y = w0*a.y + w1*b.y + c.y;
        r.z = w0*a.z + w1*b.z + c.z;
        r.w = w0*a.w + w1*b.w + c.w;
        o[d] = r;
    }
}

// ---------------- launch ----------------
extern "C" void kernel_launch(void* const* d_in, const int* in_sizes, int n_in,
                              void* d_out, int out_size)
{
    const float* x    = (const float*)d_in[0];
    const float* gw   = (const float*)d_in[1];
    const float* w1   = (const float*)d_in[2];
    const float* b1   = (const float*)d_in[3];
    const float* w2   = (const float*)d_in[4];
    const float* b2   = (const float*)d_in[5];
    const float* w3   = (const float*)d_in[6];
    const float* b3   = (const float*)d_in[7];
    const float* sw1  = (const float*)d_in[8];
    const float* sb1  = (const float*)d_in[9];
    const float* sw2  = (const float*)d_in[10];
    const float* sb2  = (const float*)d_in[11];
    const float* sw3  = (const float*)d_in[12];
    const float* sb3  = (const float*)d_in[13];
    float* out = (float*)d_out;

    float *Xg, *h1, *h3, *Yg, *s1, *s3, *z;
    int *rmap, *smap, *ntiles, *n64;
    cudaGetSymbolAddress((void**)&Xg, g_Xg);
    cudaGetSymbolAddress((void**)&h1, g_h1);
    cudaGetSymbolAddress((void**)&h3, g_h3);
    cudaGetSymbolAddress((void**)&Yg, g_Yg);
    cudaGetSymbolAddress((void**)&s1, g_s1);
    cudaGetSymbolAddress((void**)&s3, g_s3);
    cudaGetSymbolAddress((void**)&z,  g_z);
    cudaGetSymbolAddress((void**)&rmap,   g_rmap);
    cudaGetSymbolAddress((void**)&smap,   g_smap);
    cudaGetSymbolAddress((void**)&ntiles, g_ntiles);
    cudaGetSymbolAddress((void**)&n64,    g_n64);

    const int WS = DM * DM;   // per-expert weight stride
    const int BS = DM;        // per-expert bias stride

    k_zero<<<1, 32>>>();
    k_gate<<<NTOK, 256>>>(x, gw);
    k_scan<<<1, 64>>>();
    k_zeropad<<<dim3(NE, 127), 256>>>();
    k_gather<<<NTOK * 2, 256>>>(x);

    // routed experts
    k_gemm<<<dim3(RGRID, 8), 256>>>(Xg, w1, b1, h1, rmap, ntiles, WS, BS);
    k_gemm<<<dim3(RGRID, 8), 256>>>(Xg, w3, b3, h3, rmap, ntiles, WS, BS);
    k_silu<<<(MAXROWS * DM / 4 + 255) / 256, 256>>>(h1, h3, MAXROWS * DM / 4);
    k_gemm<<<dim3(RGRID, 8), 256>>>(h1, w2, b2, Yg, rmap, ntiles, WS, BS);

    // shared expert
    k_gemm<<<dim3(64, 8), 256>>>(x,  sw1, sb1, s1, smap, n64, 0, 0);
    k_gemm<<<dim3(64, 8), 256>>>(x,  sw3, sb3, s3, smap, n64, 0, 0);
    k_silu<<<(NTOK * DM / 4 + 255) / 256, 256>>>(s1, s3, NTOK * DM / 4);
    k_gemm<<<dim3(64, 8), 256>>>(s1, sw2, sb2, z, smap, n64, 0, 0);

    k_combine<<<NTOK, 256>>>(Yg, z, out);
}

// round 4
// speedup vs baseline: 2.5486x; 2.5486x over previous
#include <cuda_runtime.h>
#include <cuda_bf16.h>
#include <cstdint>
#include <math.h>

// ---------------- problem constants ----------------
#define NTOK   8192
#define DM     1024
#define NE     8
#define KP     3072      // K' = 3*DM (split-bf16 concat-K)
#define NCH    48        // KP / 64 chunks
#define MAXROWS 17408
#define RGRID  144

// ---------------- device scratch ----------------
__device__ __nv_bfloat16 g_Xs3[(size_t)NTOK   * KP];
__device__ __nv_bfloat16 g_Xg3[(size_t)MAXROWS* KP];
__device__ __nv_bfloat16 g_H3 [(size_t)MAXROWS* KP];
__device__ __nv_bfloat16 g_S3 [(size_t)NTOK   * KP];
__device__ __nv_bfloat16 g_w13[(size_t)NE * DM * KP];
__device__ __nv_bfloat16 g_w23[(size_t)NE * DM * KP];
__device__ __nv_bfloat16 g_w33[(size_t)NE * DM * KP];
__device__ __nv_bfloat16 g_sw13[(size_t)DM * KP];
__device__ __nv_bfloat16 g_sw23[(size_t)DM * KP];
__device__ __nv_bfloat16 g_sw33[(size_t)DM * KP];
__device__ float g_h1[(size_t)MAXROWS * DM];
__device__ float g_h3[(size_t)MAXROWS * DM];
__device__ float g_Yg[(size_t)MAXROWS * DM];
__device__ float g_s1[(size_t)NTOK * DM];
__device__ float g_s3[(size_t)NTOK * DM];
__device__ float g_z [(size_t)NTOK * DM];

__device__ int   g_top_idx[NTOK * 2];
__device__ float g_top_w  [NTOK * 2];
__device__ int   g_slot_row[NTOK * 2];
__device__ int   g_counts[NE];
__device__ int   g_cursor[NE];
__device__ int   g_rowbase[NE];
__device__ int   g_rmap[160];
__device__ int   g_smap[64];
__device__ int   g_ntiles[1];
__device__ int   g_n64[1];

// ---------------- helpers ----------------
__device__ __forceinline__ uint32_t smem_u32(const void* p) {
    uint32_t a;
    asm("{ .reg .u64 t; cvta.to.shared.u64 t, %1; cvt.u32.u64 %0, t; }"
        : "=r"(a) : "l"(p));
    return a;
}
__device__ __forceinline__ void cp16(uint32_t dst, const void* src) {
    asm volatile("cp.async.cg.shared.global [%0], [%1], 16;\n"
                 :: "r"(dst), "l"(src) : "memory");
}
__device__ __forceinline__ void ldm_x4(uint32_t* r, uint32_t addr) {
    asm volatile("ldmatrix.sync.aligned.m8n8.x4.shared.b16 {%0,%1,%2,%3}, [%4];"
                 : "=r"(r[0]), "=r"(r[1]), "=r"(r[2]), "=r"(r[3]) : "r"(addr));
}
__device__ __forceinline__ void mma_bf16(float* d, const uint32_t* a, const uint32_t* b) {
    asm volatile(
        "mma.sync.aligned.m16n8k16.row.col.f32.bf16.bf16.f32 "
        "{%0,%1,%2,%3}, {%4,%5,%6,%7}, {%8,%9}, {%0,%1,%2,%3};"
        : "+f"(d[0]), "+f"(d[1]), "+f"(d[2]), "+f"(d[3])
        : "r"(a[0]), "r"(a[1]), "r"(a[2]), "r"(a[3]), "r"(b[0]), "r"(b[1]));
}
__device__ __forceinline__ void split2(float v, unsigned short& hi, unsigned short& lo) {
    __nv_bfloat16 h = __float2bfloat16(v);
    float r = v - __bfloat162float(h);
    __nv_bfloat16 l = __float2bfloat16(r);
    hi = *reinterpret_cast<unsigned short*>(&h);
    lo = *reinterpret_cast<unsigned short*>(&l);
}
__device__ __forceinline__ uint32_t pk(unsigned short a, unsigned short b) {
    return (uint32_t)a | ((uint32_t)b << 16);
}

// ---------------- routing kernels ----------------
__global__ void k_zero()
{
    int i = threadIdx.x;
    if (i < NE) { g_counts[i] = 0; g_cursor[i] = 0; }
}

__global__ void k_gate(const float* __restrict__ x, const float* __restrict__ gw)
{
    int t = blockIdx.x;
    int warp = threadIdx.x >> 5, lane = threadIdx.x & 31;
    __shared__ float logits[NE];

    const float* xr = x + (size_t)t * DM;
    const float* g  = gw + (size_t)warp * DM;
    float s = 0.f;
    for (int d = lane; d < DM; d += 32) s += xr[d] * g[d];
    #pragma unroll
    for (int o = 16; o; o >>= 1) s += __shfl_xor_sync(0xffffffffu, s, o);
    if (lane == 0) logits[warp] = s;
    __syncthreads();

    if (threadIdx.x == 0) {
        float m = logits[0];
        #pragma unroll
        for (int e = 1; e < NE; e++) m = fmaxf(m, logits[e]);
        float sum = 0.f, p[NE];
        #pragma unroll
        for (int e = 0; e < NE; e++) { p[e] = expf(logits[e] - m); sum += p[e]; }
        int i0 = 0;
        #pragma unroll
        for (int e = 1; e < NE; e++) if (logits[e] > logits[i0]) i0 = e;
        int i1 = (i0 == 0) ? 1 : 0;
        #pragma unroll
        for (int e = 0; e < NE; e++)
            if (e != i0 && logits[e] > logits[i1]) i1 = e;
        float inv = 1.f / sum;
        g_top_idx[2*t]   = i0;  g_top_w[2*t]   = p[i0] * inv;
        g_top_idx[2*t+1] = i1;  g_top_w[2*t+1] = p[i1] * inv;
        atomicAdd(&g_counts[i0], 1);
        atomicAdd(&g_counts[i1], 1);
    }
}

__global__ void k_scan()
{
    int tid = threadIdx.x;
    if (tid == 0) {
        int base = 0, nt = 0;
        for (int e = 0; e < NE; e++) {
            g_rowbase[e] = base;
            int p = ((g_counts[e] + 127) >> 7) << 7;
            for (int i = 0; i < (p >> 7); i++)
                g_rmap[nt++] = (e << 20) | (base + (i << 7));
            base += p;
        }
        g_ntiles[0] = nt;
        g_n64[0] = 64;
    }
    if (tid < 64) g_smap[tid] = tid << 7;
}

// ---------------- conversion kernels ----------------
// x (fp32 [rows,DM]) -> out (bf16 [rows,KP]) pattern per k: (hi, hi, lo)  [A operand]
__global__ void k_cvt_a(const float* __restrict__ in, __nv_bfloat16* __restrict__ out, int n4)
{
    int q = blockIdx.x * blockDim.x + threadIdx.x;
    if (q >= n4) return;
    int row = q >> 8;           // DM/4 = 256
    int kq  = q & 255;
    float4 v = *(const float4*)(in + (size_t)q * 4);
    unsigned short h0,l0,h1,l1,h2,l2,h3,l3;
    split2(v.x, h0, l0); split2(v.y, h1, l1);
    split2(v.z, h2, l2); split2(v.w, h3, l3);
    char* ob = (char*)out + (size_t)row * (KP*2) + (size_t)kq * 24;
    ((uint2*)(ob +  0))[0] = make_uint2(pk(h0,h0), pk(l0,h1));
    ((uint2*)(ob +  8))[0] = make_uint2(pk(h1,l1), pk(h2,h2));
    ((uint2*)(ob + 16))[0] = make_uint2(pk(l2,h3), pk(h3,l3));
}

// silu(a)*b fused with split-convert, pattern (hi, hi, lo)
__global__ void k_silu_cvt(const float* __restrict__ a, const float* __restrict__ b,
                           __nv_bfloat16* __restrict__ out, int n4)
{
    int q = blockIdx.x * blockDim.x + threadIdx.x;
    if (q >= n4) return;
    int row = q >> 8;
    int kq  = q & 255;
    float4 va = *(const float4*)(a + (size_t)q * 4);
    float4 vb = *(const float4*)(b + (size_t)q * 4);
    float4 v;
    v.x = va.x / (1.f + expf(-va.x)) * vb.x;
    v.y = va.y / (1.f + expf(-va.y)) * vb.y;
    v.z = va.z / (1.f + expf(-va.z)) * vb.z;
    v.w = va.w / (1.f + expf(-va.w)) * vb.w;
    unsigned short h0,l0,h1,l1,h2,l2,h3,l3;
    split2(v.x, h0, l0); split2(v.y, h1, l1);
    split2(v.z, h2, l2); split2(v.w, h3, l3);
    char* ob = (char*)out + (size_t)row * (KP*2) + (size_t)kq * 24;
    ((uint2*)(ob +  0))[0] = make_uint2(pk(h0,h0), pk(l0,h1));
    ((uint2*)(ob +  8))[0] = make_uint2(pk(h1,l1), pk(h2,h2));
    ((uint2*)(ob + 16))[0] = make_uint2(pk(l2,h3), pk(h3,l3));
}

// W fp32 [K=DM, N=DM] (grid.z selects matrix) -> out bf16 [N, KP] K-major,
// pattern per k: (hi, lo, hi)  [B operand]
__global__ void k_cvt_w(const float* __restrict__ W, __nv_bfloat16* __restrict__ out)
{
    __shared__ float tile[32][33];
    int k0 = blockIdx.x << 5, n0 = blockIdx.y << 5;
    const float* Wm = W + (size_t)blockIdx.z * DM * DM;
    char* Om = (char*)out + (size_t)blockIdx.z * DM * (KP*2);
    int tx = threadIdx.x, ty = threadIdx.y;
    #pragma unroll
    for (int i = 0; i < 4; i++)
        tile[ty + i*8][tx] = Wm[(size_t)(k0 + ty + i*8) * DM + n0 + tx];
    __syncthreads();
    int tid = ty * 32 + tx;
    int wn = tid >> 3, wk4 = (tid & 7) << 2;
    char* ob = Om + (size_t)(n0 + wn) * (KP*2) + (size_t)(k0 + wk4) * 6;
    unsigned short h0,l0,h1,l1,h2,l2,h3,l3;
    split2(tile[wk4+0][wn], h0, l0);
    split2(tile[wk4+1][wn], h1, l1);
    split2(tile[wk4+2][wn], h2, l2);
    split2(tile[wk4+3][wn], h3, l3);
    ((uint2*)(ob +  0))[0] = make_uint2(pk(h0,l0), pk(h0,h1));
    ((uint2*)(ob +  8))[0] = make_uint2(pk(l1,h1), pk(h2,l2));
    ((uint2*)(ob + 16))[0] = make_uint2(pk(h2,h3), pk(l3,h3));
}

__global__ void k_zeropad3()
{
    int e = blockIdx.x;
    int c = g_counts[e];
    int p = ((c + 127) >> 7) << 7;
    int r = c + blockIdx.y;
    if (r < p) {
        uint4* row = (uint4*)(g_Xg3 + (size_t)(g_rowbase[e] + r) * KP);
        for (int i = threadIdx.x; i < KP*2/16; i += blockDim.x)
            row[i] = make_uint4(0,0,0,0);
    }
}

__global__ void k_gather3()
{
    int slot = blockIdx.x, t = slot >> 1;
    __shared__ int srow;
    if (threadIdx.x == 0) {
        int e  = g_top_idx[slot];
        int rk = atomicAdd(&g_cursor[e], 1);
        int row = g_rowbase[e] + rk;
        g_slot_row[slot] = row;
        srow = row;
    }
    __syncthreads();
    const uint4* src = (const uint4*)(g_Xs3 + (size_t)t * KP);
    uint4*       dst = (uint4*)(g_Xg3 + (size_t)srow * KP);
    for (int i = threadIdx.x; i < KP*2/16; i += blockDim.x) dst[i] = src[i];
}

// ---------------- mma.sync GEMM ----------------
// C[r0:r0+128, c0:c0+128] = A3[tile] (bf16 [*,KP]) @ W3[e] (bf16 [DM,KP] K-major)^T + bias
// 256 threads, 8 warps as 2(M) x 4(N); warp tile 64x32; Kc = 64; 3-stage cp.async.
__global__ __launch_bounds__(256)
void k_gemm_mma(const __nv_bfloat16* __restrict__ A3,
                const __nv_bfloat16* __restrict__ W3,
                const float* __restrict__ bias,
                float* __restrict__ C,
                const int* __restrict__ map,
                const int* __restrict__ ntiles,
                int wstride, int bstride)
{
    if ((int)blockIdx.x >= *ntiles) return;
    extern __shared__ char dynsmem[];

    int entry = map[blockIdx.x];
    int e = entry >> 20, r0 = entry & 0xFFFFF;
    int c0 = blockIdx.y << 7;
    int tid = threadIdx.x, wid = tid >> 5, lane = tid & 31;
    int wr = wid & 1, wc = wid >> 1;

    uint32_t sbase = smem_u32(dynsmem);
    const char* Ag = (const char*)(A3 + (size_t)r0 * KP);
    const char* Bg = (const char*)(W3 + (size_t)e * wstride + (size_t)c0 * KP);

    // stage s: A at sbase + s*32768 (128 rows x 128B, swizzled), B at +16384
    int lrow = tid >> 3, lc = tid & 7;
    uint32_t lsw = (uint32_t)(lrow*128 + ((lc ^ (lrow & 7)) << 4));

    auto load_stage = [&](int s, int ch) {
        uint32_t sa = sbase + s * 32768;
        uint32_t sb = sa + 16384;
        const char* Ac = Ag + ch * 128;
        const char* Bc = Bg + ch * 128;
        size_t goff = (size_t)lrow * (KP*2) + lc * 16;
        #pragma unroll
        for (int i = 0; i < 4; i++)
            cp16(sa + lsw + i*4096, Ac + goff + (size_t)i*32*(KP*2));
        #pragma unroll
        for (int i = 0; i < 4; i++)
            cp16(sb + lsw + i*4096, Bc + goff + (size_t)i*32*(KP*2));
        asm volatile("cp.async.commit_group;" ::: "memory");
    };

    float acc[4][4][4];
    #pragma unroll
    for (int mt = 0; mt < 4; mt++)
        #pragma unroll
        for (int nt = 0; nt < 4; nt++)
            #pragma unroll
            for (int j = 0; j < 4; j++) acc[mt][nt][j] = 0.f;

    load_stage(0, 0);
    load_stage(1, 1);
    load_stage(2, 2);

    // precomputed ldmatrix lane addressing
    int a_row = wr*64 + (lane & 15);
    int a_cb  = (lane >> 4);            // +0/+1 16B chunk within k16 pair
    int b_row = wc*32 + ((lane >> 4) << 3) + (lane & 7);
    int b_cb  = ((lane >> 3) & 1);

    for (int ch = 0; ch < NCH; ch++) {
        int s = ch % 3;
        asm volatile("cp.async.wait_group 2;" ::: "memory");
        __syncthreads();
        uint32_t sa = sbase + s * 32768;
        uint32_t sb = sa + 16384;

        #pragma unroll
        for (int kk = 0; kk < 4; kk++) {
            uint32_t a[4][4], b[4][2];
            #pragma unroll
            for (int mt = 0; mt < 4; mt++) {
                int row = a_row + mt*16;
                int c = kk*2 + a_cb;
                ldm_x4(a[mt], sa + row*128 + ((c ^ (row & 7)) << 4));
            }
            #pragma unroll
            for (int np = 0; np < 2; np++) {
                int row = b_row + np*16;
                int c = kk*2 + b_cb;
                uint32_t r4[4];
                ldm_x4(r4, sb + row*128 + ((c ^ (row & 7)) << 4));   // non-trans: smem [n][k] is already col-major B
                b[np*2][0]   = r4[0]; b[np*2][1]   = r4[1];
                b[np*2+1][0] = r4[2]; b[np*2+1][1] = r4[3];
            }
            #pragma unroll
            for (int mt = 0; mt < 4; mt++)
                #pragma unroll
                for (int nt = 0; nt < 4; nt++)
                    mma_bf16(acc[mt][nt], a[mt], b[nt]);
        }
        __syncthreads();
        if (ch + 3 < NCH) load_stage(s, ch + 3);
        else asm volatile("cp.async.commit_group;" ::: "memory");
    }

    // epilogue
    int g = lane >> 2, t4 = lane & 3;
    const float* bp = bias + (size_t)e * bstride + c0;
    #pragma unroll
    for (int mt = 0; mt < 4; mt++) {
        #pragma unroll
        for (int nt = 0; nt < 4; nt++) {
            int col = wc*32 + nt*8 + t4*2;
            float b0 = bp[col], b1 = bp[col+1];
            int row0 = r0 + wr*64 + mt*16 + g;
            float2 v0 = make_float2(acc[mt][nt][0] + b0, acc[mt][nt][1] + b1);
            float2 v1 = make_float2(acc[mt][nt][2] + b0, acc[mt][nt][3] + b1);
            *(float2*)(C + (size_t)row0 * DM + c0 + col)     = v0;
            *(float2*)(C + (size_t)(row0+8) * DM + c0 + col) = v1;
        }
    }
}

// ---------------- combine ----------------
__global__ void k_combine(const float* __restrict__ Yg, const float* __restrict__ z,
                          float* __restrict__ out)
{
    int t = blockIdx.x;
    int r0 = g_slot_row[2*t], r1 = g_slot_row[2*t+1];
    float w0 = g_top_w[2*t], w1 = g_top_w[2*t+1];
    const float4* y0 = (const float4*)(Yg + (size_t)r0 * DM);
    const float4* y1 = (const float4*)(Yg + (size_t)r1 * DM);
    const float4* zz = (const float4*)(z  + (size_t)t  * DM);
    float4*       o  = (float4*)(out + (size_t)t * DM);
    for (int d = threadIdx.x; d < DM/4; d += blockDim.x) {
        float4 a = y0[d], b = y1[d], c = zz[d], r;
        r.x = w0*a.x + w1*b.x + c.x;
        r.y = w0*a.y + w1*b.y + c.y;
        r.z = w0*a.z + w1*b.z + c.z;
        r.w = w0*a.w + w1*b.w + c.w;
        o[d] = r;
    }
}

// ---------------- launch ----------------
extern "C" void kernel_launch(void* const* d_in, const int* in_sizes, int n_in,
                              void* d_out, int out_size)
{
    const float* x    = (const float*)d_in[0];
    const float* gw   = (const float*)d_in[1];
    const float* w1   = (const float*)d_in[2];
    const float* b1   = (const float*)d_in[3];
    const float* w2   = (const float*)d_in[4];
    const float* b2   = (const float*)d_in[5];
    const float* w3   = (const float*)d_in[6];
    const float* b3   = (const float*)d_in[7];
    const float* sw1  = (const float*)d_in[8];
    const float* sb1  = (const float*)d_in[9];
    const float* sw2  = (const float*)d_in[10];
    const float* sb2  = (const float*)d_in[11];
    const float* sw3  = (const float*)d_in[12];
    const float* sb3  = (const float*)d_in[13];
    float* out = (float*)d_out;

    __nv_bfloat16 *Xs3, *Xg3, *H3, *S3, *w13, *w23, *w33, *sw13, *sw23, *sw33;
    float *h1, *h3, *Yg, *s1, *s3, *z;
    int *rmap, *smap, *ntiles, *n64;
    cudaGetSymbolAddress((void**)&Xs3, g_Xs3);
    cudaGetSymbolAddress((void**)&Xg3, g_Xg3);
    cudaGetSymbolAddress((void**)&H3,  g_H3);
    cudaGetSymbolAddress((void**)&S3,  g_S3);
    cudaGetSymbolAddress((void**)&w13, g_w13);
    cudaGetSymbolAddress((void**)&w23, g_w23);
    cudaGetSymbolAddress((void**)&w33, g_w33);
    cudaGetSymbolAddress((void**)&sw13, g_sw13);
    cudaGetSymbolAddress((void**)&sw23, g_sw23);
    cudaGetSymbolAddress((void**)&sw33, g_sw33);
    cudaGetSymbolAddress((void**)&h1, g_h1);
    cudaGetSymbolAddress((void**)&h3, g_h3);
    cudaGetSymbolAddress((void**)&Yg, g_Yg);
    cudaGetSymbolAddress((void**)&s1, g_s1);
    cudaGetSymbolAddress((void**)&s3, g_s3);
    cudaGetSymbolAddress((void**)&z,  g_z);
    cudaGetSymbolAddress((void**)&rmap,   g_rmap);
    cudaGetSymbolAddress((void**)&smap,   g_smap);
    cudaGetSymbolAddress((void**)&ntiles, g_ntiles);
    cudaGetSymbolAddress((void**)&n64,    g_n64);

    const int SMEM = 3 * 32768;
    cudaFuncSetAttribute(k_gemm_mma, cudaFuncAttributeMaxDynamicSharedMemorySize, SMEM);

    k_zero<<<1, 32>>>();
    k_gate<<<NTOK, 256>>>(x, gw);
    k_scan<<<1, 64>>>();

    // conversions
    k_cvt_a<<<(NTOK*DM/4 + 255)/256, 256>>>(x, Xs3, NTOK*DM/4);
    k_cvt_w<<<dim3(32,32,NE), dim3(32,8)>>>(w1, w13);
    k_cvt_w<<<dim3(32,32,NE), dim3(32,8)>>>(w2, w23);
    k_cvt_w<<<dim3(32,32,NE), dim3(32,8)>>>(w3, w33);
    k_cvt_w<<<dim3(32,32,1),  dim3(32,8)>>>(sw1, sw13);
    k_cvt_w<<<dim3(32,32,1),  dim3(32,8)>>>(sw2, sw23);
    k_cvt_w<<<dim3(32,32,1),  dim3(32,8)>>>(sw3, sw33);

    k_zeropad3<<<dim3(NE, 127), 256>>>();
    k_gather3<<<NTOK*2, 128>>>();

    const int WS = DM * KP;
    // routed experts
    k_gemm_mma<<<dim3(RGRID,8), 256, SMEM>>>(Xg3, w13, b1, h1, rmap, ntiles, WS, DM);
    k_gemm_mma<<<dim3(RGRID,8), 256, SMEM>>>(Xg3, w33, b3, h3, rmap, ntiles, WS, DM);
    k_silu_cvt<<<(MAXROWS*DM/4 + 255)/256, 256>>>(h1, h3, H3, MAXROWS*DM/4);
    k_gemm_mma<<<dim3(RGRID,8), 256, SMEM>>>(H3, w23, b2, Yg, rmap, ntiles, WS, DM);

    // shared expert
    k_gemm_mma<<<dim3(64,8), 256, SMEM>>>(Xs3, sw13, sb1, s1, smap, n64, 0, 0);
    k_gemm_mma<<<dim3(64,8), 256, SMEM>>>(Xs3, sw33, sb3, s3, smap, n64, 0, 0);
    k_silu_cvt<<<(NTOK*DM/4 + 255)/256, 256>>>(s1, s3, S3, NTOK*DM/4);
    k_gemm_mma<<<dim3(64,8), 256, SMEM>>>(S3, sw23, sb2, z, smap, n64, 0, 0);

    k_combine<<<NTOK, 256>>>(Yg, z, out);
}